// round 12
// baseline (speedup 1.0000x reference)
#include <cuda_runtime.h>
#include <cuda_bf16.h>
#include <cstdint>

// ---------------------------------------------------------------------------
// B=4, S=2048, D=1024. All GEMMs on mma.sync.m16n8k16 bf16 with 2-term bf16
// operand splitting (hi*hi + hi*lo + lo*hi) for fp32-class accuracy.
// R11: 4-stage cp.async pipeline (KC=32, 48KB/stage), one barrier per chunk,
// load-issue before compute, precomputed loader addresses (hi/lo merged).
// ---------------------------------------------------------------------------

#define BATCH 4
#define SEQ   2048
#define DIM   1024

#define BM 128
#define BN 256
#define KC 32                       // bf16 per K chunk = 64 bytes/row
#define THREADS 512
#define NSTAGE 4

#define OFF_AH 0
#define OFF_AL 8192                 // A: 128 rows x 64B per split
#define OFF_BH 16384                // B: 256 rows x 64B per split
#define OFF_BL 32768
#define STAGE_BYTES 49152           // 48 KB
#define SMEM_TOTAL (NSTAGE * STAGE_BYTES)   // 192 KB

#define EP_LD 260                   // epilogue smem row stride (u32)

#define N_IN  ((size_t)BATCH * SEQ * DIM)   // 8388608
#define N_W   ((size_t)DIM * DIM)           // 1048576
#define N_S   ((size_t)BATCH * SEQ * SEQ)   // 16777216

// ------------- device-global scratch: hi half at [0,N), lo at [N,2N) -------
__device__ __nv_bfloat16 g_qi[2 * N_IN];
__device__ __nv_bfloat16 g_ki[2 * N_IN];
__device__ __nv_bfloat16 g_vi[2 * N_IN];
__device__ __nv_bfloat16 g_wq[2 * N_W];
__device__ __nv_bfloat16 g_wk[2 * N_W];
__device__ __nv_bfloat16 g_wv[2 * N_W];
__device__ __nv_bfloat16 g_Q [2 * N_IN];
__device__ __nv_bfloat16 g_K [2 * N_IN];
__device__ __nv_bfloat16 g_Vt[2 * N_IN];    // [b][d][s]
__device__ __nv_bfloat16 g_S [2 * N_S];

// ----------------------------- asm helpers --------------------------------
__device__ __forceinline__ uint32_t smem_u32(const void* p) {
    uint32_t a;
    asm("{ .reg .u64 t; cvta.to.shared.u64 t, %1; cvt.u32.u64 %0, t; }"
        : "=r"(a) : "l"(p));
    return a;
}

__device__ __forceinline__ void cp16(uint32_t dst, const void* src) {
    asm volatile("cp.async.cg.shared.global [%0], [%1], 16;" :: "r"(dst), "l"(src));
}

#define CP_COMMIT() asm volatile("cp.async.commit_group;" ::: "memory")

#define LDSM4(r, addr) \
    asm volatile("ldmatrix.sync.aligned.m8n8.x4.shared.b16 {%0,%1,%2,%3}, [%4];" \
        : "=r"((r)[0]), "=r"((r)[1]), "=r"((r)[2]), "=r"((r)[3]) : "r"(addr))

#define MMA(c, a, b0, b1) \
    asm volatile("mma.sync.aligned.m16n8k16.row.col.f32.bf16.bf16.f32 " \
        "{%0,%1,%2,%3}, {%4,%5,%6,%7}, {%8,%9}, {%0,%1,%2,%3};" \
        : "+f"((c)[0]), "+f"((c)[1]), "+f"((c)[2]), "+f"((c)[3]) \
        : "r"((a)[0]), "r"((a)[1]), "r"((a)[2]), "r"((a)[3]), "r"(b0), "r"(b1))

// ---------------------------------------------------------------------------
// Tensor-core GEMM: C[M,N] = A[M,K] @ B[N,K]^T. A lo at A+dA, B lo at B+dB.
// 16 warps: warp grid 2(M) x 8(N), warp tile 64x32.
// MODE 0: fp32 out ; MODE 1: split bf16 out (Ch/Cl row-major) ;
// MODE 2: split bf16 out transposed per-batch into [b][n][m%SEQ] (Vt).
// ---------------------------------------------------------------------------
template <int MODE, bool RELU, bool BIAS>
__global__ __launch_bounds__(THREADS, 1)
void tc_gemm(const __nv_bfloat16* __restrict__ A, long long dA,
             const __nv_bfloat16* __restrict__ B, long long dB,
             const float* __restrict__ bias,
             float* __restrict__ Cf,
             __nv_bfloat16* __restrict__ Ch, __nv_bfloat16* __restrict__ Cl,
             int K, int ldc, long long sA, long long sB, long long sC)
{
    extern __shared__ char smem[];
    const uint32_t su = smem_u32(smem);
    const int tid  = threadIdx.x;
    const int lane = tid & 31;
    const int wid  = tid >> 5;
    const int warp_m = (wid & 1) * 64;
    const int warp_n = (wid >> 1) * 32;
    const int bm = blockIdx.y * BM;
    const int bn = blockIdx.x * BN;
    const int z  = blockIdx.z;
    A += (long long)z * sA;
    B += (long long)z * sB;

    // ---- loader precompute: each thread owns fixed (row, chunk) slots ----
    const int ra = tid >> 2, ca = tid & 3;          // A: 128 rows x 4 chunks
    const __nv_bfloat16* pA = A + (long long)(bm + ra) * K + ca * 8;
    const uint32_t smA = (uint32_t)(OFF_AH + ra * 64 + ((ca ^ ((ra >> 1) & 3)) << 4));
    const __nv_bfloat16* pB = B + (long long)(bn + ra) * K + ca * 8;  // rows ra, ra+128
    const uint32_t smB = (uint32_t)(OFF_BH + ra * 64 + ((ca ^ ((ra >> 1) & 3)) << 4));
    const long long bstep = (long long)128 * K;

    auto LOAD = [&](int chunk) {
        uint32_t sb = su + (uint32_t)(chunk & 3) * STAGE_BYTES;
        const __nv_bfloat16* a = pA + chunk * KC;
        const __nv_bfloat16* b = pB + chunk * KC;
        cp16(sb + smA,                 a);
        cp16(sb + smA + OFF_AL,        a + dA);
        cp16(sb + smB,                 b);
        cp16(sb + smB + 8192,          b + bstep);
        cp16(sb + smB + 16384,         b + dB);
        cp16(sb + smB + 16384 + 8192,  b + dB + bstep);
        CP_COMMIT();
    };

    float acc[4][4][4];
#pragma unroll
    for (int i = 0; i < 4; i++)
#pragma unroll
        for (int j = 0; j < 4; j++)
#pragma unroll
            for (int k = 0; k < 4; k++) acc[i][j][k] = 0.0f;

    const int nc = K / KC;

    LOAD(0); LOAD(1); LOAD(2);

    // per-lane ldmatrix addressing
    const int arow  = ((lane >> 3) & 1) * 8 + (lane & 7);
    const int chalf = lane >> 4;
    const int swsel = (arow >> 1) & 3;

    for (int i = 0; i < nc; i++) {
        const int rem = nc - 1 - i;
        if (rem >= 2)      asm volatile("cp.async.wait_group 2;" ::: "memory");
        else if (rem == 1) asm volatile("cp.async.wait_group 1;" ::: "memory");
        else               asm volatile("cp.async.wait_group 0;" ::: "memory");
        __syncthreads();

        if (i + 3 < nc) LOAD(i + 3);   // issued BEFORE compute; buffer freed by i-1

        const uint32_t sb = su + (uint32_t)(i & 3) * STAGE_BYTES;
        const uint32_t aRow = sb + OFF_AH + (uint32_t)(warp_m + arow) * 64u;
        const uint32_t bRow = sb + OFF_BH + (uint32_t)(warp_n + arow) * 64u;

#pragma unroll
        for (int ks = 0; ks < 2; ks++) {
            const uint32_t cb = (uint32_t)(((ks * 2 + chalf) ^ swsel) << 4);
            uint32_t fbh[2][4], fbl[2][4];
#pragma unroll
            for (int jn = 0; jn < 2; jn++) {
                LDSM4(fbh[jn], bRow + jn * 1024u + cb);
                LDSM4(fbl[jn], bRow + 16384u + jn * 1024u + cb);
            }
#pragma unroll
            for (int im = 0; im < 4; im++) {
                uint32_t fah[4], fal[4];
                LDSM4(fah, aRow + im * 1024u + cb);
                LDSM4(fal, aRow + 8192u + im * 1024u + cb);
#pragma unroll
                for (int jn = 0; jn < 2; jn++) {
                    MMA(acc[im][2 * jn],     fah, fbh[jn][0], fbh[jn][2]);
                    MMA(acc[im][2 * jn + 1], fah, fbh[jn][1], fbh[jn][3]);
                }
#pragma unroll
                for (int jn = 0; jn < 2; jn++) {
                    MMA(acc[im][2 * jn],     fah, fbl[jn][0], fbl[jn][2]);
                    MMA(acc[im][2 * jn + 1], fah, fbl[jn][1], fbl[jn][3]);
                }
#pragma unroll
                for (int jn = 0; jn < 2; jn++) {
                    MMA(acc[im][2 * jn],     fal, fbh[jn][0], fbh[jn][2]);
                    MMA(acc[im][2 * jn + 1], fal, fbh[jn][1], fbh[jn][3]);
                }
            }
        }
    }
    __syncthreads();   // protect smem reuse by epilogue

    // ---- epilogue: regs -> smem stage (bias/relu/convert) -> coalesced gmem ----
    uint32_t* stage = (uint32_t*)smem;
#pragma unroll
    for (int im = 0; im < 4; im++) {
#pragma unroll
        for (int j8 = 0; j8 < 4; j8++) {
            int r0 = warp_m + im * 16 + (lane >> 2);
            int c0 = warp_n + j8 * 8 + (lane & 3) * 2;
#pragma unroll
            for (int half = 0; half < 2; half++) {
                int r = r0 + half * 8;
#pragma unroll
                for (int cc = 0; cc < 2; cc++) {
                    float v = acc[im][j8][half * 2 + cc];
                    int c = c0 + cc;
                    if (BIAS) v += bias[bn + c];
                    if (RELU) v = fmaxf(v, 0.0f);
                    uint32_t w;
                    if (MODE == 0) {
                        w = __float_as_uint(v);
                    } else {
                        __nv_bfloat16 h = __float2bfloat16_rn(v);
                        float hf = __bfloat162float(h);
                        __nv_bfloat16 l = __float2bfloat16_rn(v - hf);
                        w = (uint32_t)__bfloat16_as_ushort(h) |
                            ((uint32_t)__bfloat16_as_ushort(l) << 16);
                    }
                    stage[r * EP_LD + c] = w;
                }
            }
        }
    }
    __syncthreads();

    if (MODE == 0) {
        float* Cp = Cf + (long long)z * sC;
#pragma unroll 4
        for (int k2 = 0; k2 < 64; k2++) {
            int idx = tid + k2 * THREADS;
            int r = idx >> 8, c = idx & 255;
            Cp[(long long)(bm + r) * ldc + bn + c] =
                __uint_as_float(stage[r * EP_LD + c]);
        }
    } else if (MODE == 1) {
        __nv_bfloat16* ChP = Ch + (long long)z * sC;
        __nv_bfloat16* ClP = Cl + (long long)z * sC;
#pragma unroll 4
        for (int k2 = 0; k2 < 32; k2++) {
            int p = tid + k2 * THREADS;
            int r = p >> 7, cp2 = (p & 127) * 2;
            uint32_t w0 = stage[r * EP_LD + cp2];
            uint32_t w1 = stage[r * EP_LD + cp2 + 1];
            uint32_t hw = (w0 & 0xFFFFu) | (w1 << 16);
            uint32_t lw = (w0 >> 16) | (w1 & 0xFFFF0000u);
            long long o = (long long)(bm + r) * ldc + bn + cp2;
            *(uint32_t*)(ChP + o) = hw;
            *(uint32_t*)(ClP + o) = lw;
        }
    } else {
        // Vt[b][d][s]: b = bm/SEQ, d = bn+c, s = bm%SEQ + r
        long long ob = (long long)(bm >> 11) * ((long long)DIM * SEQ);
        int sbase = bm & (SEQ - 1);
#pragma unroll 1
        for (int cc = 0; cc < 16; cc++) {
            int c = (tid >> 5) + cc * 16;
#pragma unroll
            for (int rr = 0; rr < 4; rr++) {
                int r = (tid & 31) + rr * 32;
                uint32_t w = stage[r * EP_LD + c];
                long long o = ob + (long long)(bn + c) * SEQ + sbase + r;
                Ch[o] = __ushort_as_bfloat16((unsigned short)(w & 0xFFFF));
                Cl[o] = __ushort_as_bfloat16((unsigned short)(w >> 16));
            }
        }
    }
}

// ------------- fp32 -> bf16 hi/lo split (single fused launch) --------------
__global__ __launch_bounds__(256)
void split_all_kernel(const float* __restrict__ q, const float* __restrict__ k,
                      const float* __restrict__ v, const float* __restrict__ wq,
                      const float* __restrict__ wk, const float* __restrict__ wv,
                      __nv_bfloat16* __restrict__ qh, __nv_bfloat16* __restrict__ kh,
                      __nv_bfloat16* __restrict__ vh, __nv_bfloat16* __restrict__ wqh,
                      __nv_bfloat16* __restrict__ wkh, __nv_bfloat16* __restrict__ wvh)
{
    int b = blockIdx.x;
    const float* x;
    __nv_bfloat16* h;
    long long loff;
    int off;
    if      (b < 8192)  { x = q;  h = qh;  loff = N_IN; off = b; }
    else if (b < 16384) { x = k;  h = kh;  loff = N_IN; off = b - 8192; }
    else if (b < 24576) { x = v;  h = vh;  loff = N_IN; off = b - 16384; }
    else if (b < 25600) { x = wq; h = wqh; loff = N_W;  off = b - 24576; }
    else if (b < 26624) { x = wk; h = wkh; loff = N_W;  off = b - 25600; }
    else                { x = wv; h = wvh; loff = N_W;  off = b - 26624; }

    int i = off * 1024 + threadIdx.x * 4;
    float4 val = *(const float4*)(x + i);
    float vv[4] = {val.x, val.y, val.z, val.w};
    unsigned short hs[4], ls[4];
#pragma unroll
    for (int j = 0; j < 4; j++) {
        __nv_bfloat16 hb = __float2bfloat16_rn(vv[j]);
        float hf = __bfloat162float(hb);
        __nv_bfloat16 lb = __float2bfloat16_rn(vv[j] - hf);
        hs[j] = __bfloat16_as_ushort(hb);
        ls[j] = __bfloat16_as_ushort(lb);
    }
    uint2 hw = make_uint2((uint32_t)hs[0] | ((uint32_t)hs[1] << 16),
                          (uint32_t)hs[2] | ((uint32_t)hs[3] << 16));
    uint2 lw = make_uint2((uint32_t)ls[0] | ((uint32_t)ls[1] << 16),
                          (uint32_t)ls[2] | ((uint32_t)ls[3] << 16));
    *(uint2*)(h + i) = hw;
    *(uint2*)(h + loff + i) = lw;
}

// ---------------------------------------------------------------------------
extern "C" void kernel_launch(void* const* d_in, const int* in_sizes, int n_in,
                              void* d_out, int out_size)
{
    const float* queries = (const float*)d_in[0];
    const float* keys    = (const float*)d_in[1];
    const float* values  = (const float*)d_in[2];
    const float* Wq      = (const float*)d_in[3];
    const float* bq      = (const float*)d_in[4];
    const float* Wk      = (const float*)d_in[5];
    const float* bk      = (const float*)d_in[6];
    const float* Wv      = (const float*)d_in[7];
    const float* bv      = (const float*)d_in[8];
    float* out = (float*)d_out;

    __nv_bfloat16 *qi, *ki, *vi, *wq, *wk, *wv, *Q, *Kp, *Vt, *S;
    cudaGetSymbolAddress((void**)&qi, g_qi);
    cudaGetSymbolAddress((void**)&ki, g_ki);
    cudaGetSymbolAddress((void**)&vi, g_vi);
    cudaGetSymbolAddress((void**)&wq, g_wq);
    cudaGetSymbolAddress((void**)&wk, g_wk);
    cudaGetSymbolAddress((void**)&wv, g_wv);
    cudaGetSymbolAddress((void**)&Q,  g_Q);
    cudaGetSymbolAddress((void**)&Kp, g_K);
    cudaGetSymbolAddress((void**)&Vt, g_Vt);
    cudaGetSymbolAddress((void**)&S,  g_S);

    cudaFuncSetAttribute(tc_gemm<1, false, true>,
                         cudaFuncAttributeMaxDynamicSharedMemorySize, SMEM_TOTAL);
    cudaFuncSetAttribute(tc_gemm<2, false, true>,
                         cudaFuncAttributeMaxDynamicSharedMemorySize, SMEM_TOTAL);
    cudaFuncSetAttribute(tc_gemm<1, true, false>,
                         cudaFuncAttributeMaxDynamicSharedMemorySize, SMEM_TOTAL);
    cudaFuncSetAttribute(tc_gemm<0, false, false>,
                         cudaFuncAttributeMaxDynamicSharedMemorySize, SMEM_TOTAL);

    // 0) split inputs + weights into bf16 hi/lo
    split_all_kernel<<<27648, 256>>>(queries, keys, values, Wq, Wk, Wv,
                                     qi, ki, vi, wq, wk, wv);

    const int Mproj = BATCH * SEQ;       // 8192
    dim3 blk(THREADS);

    // 1) projections (M=8192, N=1024, K=1024)
    dim3 gp(DIM / BN, Mproj / BM, 1);
    tc_gemm<1, false, true><<<gp, blk, SMEM_TOTAL>>>(
        qi, (long long)N_IN, wq, (long long)N_W, bq,
        nullptr, Q, Q + N_IN, DIM, DIM, 0, 0, 0);
    tc_gemm<1, false, true><<<gp, blk, SMEM_TOTAL>>>(
        ki, (long long)N_IN, wk, (long long)N_W, bk,
        nullptr, Kp, Kp + N_IN, DIM, DIM, 0, 0, 0);
    tc_gemm<2, false, true><<<gp, blk, SMEM_TOTAL>>>(
        vi, (long long)N_IN, wv, (long long)N_W, bv,
        nullptr, Vt, Vt + N_IN, DIM, 0, 0, 0, 0);

    // 2) scores: relu(Q @ K^T) per batch (M=2048, N=2048, K=1024)
    dim3 gs(SEQ / BN, SEQ / BM, BATCH);
    tc_gemm<1, true, false><<<gs, blk, SMEM_TOTAL>>>(
        Q, (long long)N_IN, Kp, (long long)N_IN, nullptr,
        nullptr, S, S + N_S, DIM, SEQ,
        (long long)SEQ * DIM, (long long)SEQ * DIM, (long long)SEQ * SEQ);

    // 3) output: S @ Vt^T per batch (M=2048, N=1024, K=2048)
    dim3 go(DIM / BN, SEQ / BM, BATCH);
    tc_gemm<0, false, false><<<go, blk, SMEM_TOTAL>>>(
        S, (long long)N_S, Vt, (long long)N_IN, nullptr,
        out, nullptr, nullptr, SEQ, DIM,
        (long long)SEQ * SEQ, (long long)DIM * SEQ, (long long)SEQ * DIM);

    (void)in_sizes; (void)n_in; (void)out_size;
}

// round 14
// speedup vs baseline: 1.5033x; 1.5033x over previous
#include <cuda_runtime.h>
#include <cuda_fp16.h>
#include <cstdint>

// ---------------------------------------------------------------------------
// B=4, S=2048, D=1024. All GEMMs on mma.sync.m16n8k16 fp16 tensor cores.
// Precision scheme (R13): A split into fp16 hi+lo, B rounded to fp16 once.
//   C = A_hi*B + A_lo*B  == (A exact to ~22 bits) * fp16(B)
// 2 MMA passes (vs 3 for bf16x3); error ~2^-12 per GEMM, chained ~2-4e-4.
// 512 threads / 16 warps, CTA tile 128x256, KC=64, 3-stage cp.async (64KB ea).
// ---------------------------------------------------------------------------

#define BATCH 4
#define SEQ   2048
#define DIM   1024

#define BM 128
#define BN 256
#define KC 64                       // fp16 per K chunk = 128 bytes/row
#define THREADS 512

#define OFF_AH 0                    // A hi: 128 rows x 128B = 16 KB
#define OFF_AL 16384                // A lo: 16 KB
#define OFF_B  32768                // B:    256 rows x 128B = 32 KB
#define STAGE_BYTES 65536           // 64 KB
#define SMEM_TOTAL (3 * STAGE_BYTES)   // 192 KB

#define EP_LD 260                   // epilogue smem row stride (u32)

#define N_IN  ((size_t)BATCH * SEQ * DIM)   // 8388608
#define N_W   ((size_t)DIM * DIM)           // 1048576
#define N_S   ((size_t)BATCH * SEQ * SEQ)   // 16777216

// ------------- device-global scratch: hi half at [0,N), lo at [N,2N) -------
__device__ __half g_qi[2 * N_IN];
__device__ __half g_ki[2 * N_IN];
__device__ __half g_vi[2 * N_IN];
__device__ __half g_wq[2 * N_W];
__device__ __half g_wk[2 * N_W];
__device__ __half g_wv[2 * N_W];
__device__ __half g_Q [2 * N_IN];
__device__ __half g_K [2 * N_IN];
__device__ __half g_Vt[2 * N_IN];    // [b][d][s]
__device__ __half g_S [2 * N_S];

// ----------------------------- asm helpers --------------------------------
__device__ __forceinline__ uint32_t smem_u32(const void* p) {
    uint32_t a;
    asm("{ .reg .u64 t; cvta.to.shared.u64 t, %1; cvt.u32.u64 %0, t; }"
        : "=r"(a) : "l"(p));
    return a;
}

__device__ __forceinline__ void cp16(uint32_t dst, const void* src) {
    asm volatile("cp.async.cg.shared.global [%0], [%1], 16;" :: "r"(dst), "l"(src));
}

#define CP_COMMIT() asm volatile("cp.async.commit_group;" ::: "memory")

#define LDSM4(r, addr) \
    asm volatile("ldmatrix.sync.aligned.m8n8.x4.shared.b16 {%0,%1,%2,%3}, [%4];" \
        : "=r"((r)[0]), "=r"((r)[1]), "=r"((r)[2]), "=r"((r)[3]) : "r"(addr))

#define MMA(c, a, b0, b1) \
    asm volatile("mma.sync.aligned.m16n8k16.row.col.f32.f16.f16.f32 " \
        "{%0,%1,%2,%3}, {%4,%5,%6,%7}, {%8,%9}, {%0,%1,%2,%3};" \
        : "+f"((c)[0]), "+f"((c)[1]), "+f"((c)[2]), "+f"((c)[3]) \
        : "r"((a)[0]), "r"((a)[1]), "r"((a)[2]), "r"((a)[3]), "r"(b0), "r"(b1))

// ---------------------------------------------------------------------------
// Tensor-core GEMM: C[M,N] = A[M,K] @ B[N,K]^T. A lo at A+dA; B single fp16.
// 16 warps: warp grid 2(M) x 8(N), warp tile 64x32.
// MODE 0: fp32 out ; MODE 1: split fp16 out (Ch hi, Cl lo, row-major) ;
// MODE 2: split fp16 out transposed per-batch into [b][n][m%SEQ] (Vt).
// ---------------------------------------------------------------------------
template <int MODE, bool RELU, bool BIAS>
__global__ __launch_bounds__(THREADS, 1)
void tc_gemm(const __half* __restrict__ A, long long dA,
             const __half* __restrict__ B,
             const float* __restrict__ bias,
             float* __restrict__ Cf,
             __half* __restrict__ Ch, __half* __restrict__ Cl,
             int K, int ldc, long long sA, long long sB, long long sC)
{
    extern __shared__ char smem[];
    const uint32_t su = smem_u32(smem);
    const int tid  = threadIdx.x;
    const int lane = tid & 31;
    const int wid  = tid >> 5;
    const int warp_m = (wid & 1) * 64;
    const int warp_n = (wid >> 1) * 32;
    const int bm = blockIdx.y * BM;
    const int bn = blockIdx.x * BN;
    const int z  = blockIdx.z;
    A += (long long)z * sA;
    B += (long long)z * sB;

    float acc[4][4][4];
#pragma unroll
    for (int i = 0; i < 4; i++)
#pragma unroll
        for (int j = 0; j < 4; j++)
#pragma unroll
            for (int k = 0; k < 4; k++) acc[i][j][k] = 0.0f;

    const int nc = K / KC;

    // Stage loader: A hi (2 its) + A lo (2 its) + B (4 its) = 8 x 16B / thread.
    auto LOAD = [&](int chunk) {
        uint32_t sb = su + (uint32_t)(chunk % 3) * STAGE_BYTES;
        int kt = chunk * KC;
#pragma unroll
        for (int it = 0; it < 8; it++) {
            int lin = it * THREADS + tid;
            const __half* gp;
            uint32_t toff;
            int c;
            if (it < 2)      { c = lin;        gp = A +      (long long)(bm + (c >> 3)) * K; toff = OFF_AH; }
            else if (it < 4) { c = lin - 1024; gp = A + dA + (long long)(bm + (c >> 3)) * K; toff = OFF_AL; }
            else             { c = lin - 2048; gp = B +      (long long)(bn + (c >> 3)) * K; toff = OFF_B; }
            int row = c >> 3;
            int c16 = c & 7;
            uint32_t dst = sb + toff + (uint32_t)row * 128u +
                           (uint32_t)((c16 ^ (row & 7)) << 4);
            cp16(dst, gp + kt + c16 * 8);
        }
        CP_COMMIT();
    };

    LOAD(0); LOAD(1);

    // per-lane ldmatrix addressing
    const int arow  = ((lane >> 3) & 1) * 8 + (lane & 7);
    const int chalf = lane >> 4;
    const int swz   = lane & 7;

    for (int i = 0; i < nc; i++) {
        if (i + 1 < nc) asm volatile("cp.async.wait_group 1;" ::: "memory");
        else            asm volatile("cp.async.wait_group 0;" ::: "memory");
        __syncthreads();

        if (i + 2 < nc) LOAD(i + 2);   // into slot (i+2)%3 == (i-1)%3, freed at sync

        const uint32_t sb = su + (uint32_t)(i % 3) * STAGE_BYTES;
        const uint32_t aRow = sb + OFF_AH + (uint32_t)(warp_m + arow) * 128u;
        const uint32_t bRow = sb + OFF_B  + (uint32_t)(warp_n + arow) * 128u;

#pragma unroll
        for (int ks = 0; ks < 4; ks++) {
            const uint32_t cb = (uint32_t)(((ks * 2 + chalf) ^ swz) << 4);
            uint32_t fb[2][4];
#pragma unroll
            for (int jn = 0; jn < 2; jn++)
                LDSM4(fb[jn], bRow + jn * 2048u + cb);
#pragma unroll
            for (int im = 0; im < 4; im++) {
                uint32_t fah[4], fal[4];
                LDSM4(fah, aRow + im * 2048u + cb);
                LDSM4(fal, aRow + 16384u + im * 2048u + cb);
                // Pass 1: A_hi * B
#pragma unroll
                for (int jn = 0; jn < 2; jn++) {
                    MMA(acc[im][2 * jn],     fah, fb[jn][0], fb[jn][2]);
                    MMA(acc[im][2 * jn + 1], fah, fb[jn][1], fb[jn][3]);
                }
                // Pass 2: A_lo * B
#pragma unroll
                for (int jn = 0; jn < 2; jn++) {
                    MMA(acc[im][2 * jn],     fal, fb[jn][0], fb[jn][2]);
                    MMA(acc[im][2 * jn + 1], fal, fb[jn][1], fb[jn][3]);
                }
            }
        }
    }
    __syncthreads();   // protect smem reuse by epilogue

    // ---- epilogue: regs -> smem stage (bias/relu/convert) -> coalesced gmem ----
    uint32_t* stage = (uint32_t*)smem;
#pragma unroll
    for (int im = 0; im < 4; im++) {
#pragma unroll
        for (int j8 = 0; j8 < 4; j8++) {
            int r0 = warp_m + im * 16 + (lane >> 2);
            int c0 = warp_n + j8 * 8 + (lane & 3) * 2;
#pragma unroll
            for (int half = 0; half < 2; half++) {
                int r = r0 + half * 8;
#pragma unroll
                for (int cc = 0; cc < 2; cc++) {
                    float v = acc[im][j8][half * 2 + cc];
                    int c = c0 + cc;
                    if (BIAS) v += bias[bn + c];
                    if (RELU) v = fmaxf(v, 0.0f);
                    uint32_t w;
                    if (MODE == 0) {
                        w = __float_as_uint(v);
                    } else {
                        __half h = __float2half_rn(v);
                        float hf = __half2float(h);
                        __half l = __float2half_rn(v - hf);
                        w = (uint32_t)__half_as_ushort(h) |
                            ((uint32_t)__half_as_ushort(l) << 16);
                    }
                    stage[r * EP_LD + c] = w;
                }
            }
        }
    }
    __syncthreads();

    if (MODE == 0) {
        float* Cp = Cf + (long long)z * sC;
#pragma unroll 4
        for (int k2 = 0; k2 < 64; k2++) {
            int idx = tid + k2 * THREADS;
            int r = idx >> 8, c = idx & 255;
            Cp[(long long)(bm + r) * ldc + bn + c] =
                __uint_as_float(stage[r * EP_LD + c]);
        }
    } else if (MODE == 1) {
        __half* ChP = Ch + (long long)z * sC;
        __half* ClP = Cl + (long long)z * sC;
#pragma unroll 4
        for (int k2 = 0; k2 < 32; k2++) {
            int p = tid + k2 * THREADS;
            int r = p >> 7, cp2 = (p & 127) * 2;
            uint32_t w0 = stage[r * EP_LD + cp2];
            uint32_t w1 = stage[r * EP_LD + cp2 + 1];
            uint32_t hw = (w0 & 0xFFFFu) | (w1 << 16);
            uint32_t lw = (w0 >> 16) | (w1 & 0xFFFF0000u);
            long long o = (long long)(bm + r) * ldc + bn + cp2;
            *(uint32_t*)(ChP + o) = hw;
            *(uint32_t*)(ClP + o) = lw;
        }
    } else {
        // Vt[b][d][s]: b = bm/SEQ, d = bn+c, s = bm%SEQ + r
        long long ob = (long long)(bm >> 11) * ((long long)DIM * SEQ);
        int sbase = bm & (SEQ - 1);
#pragma unroll 1
        for (int cc = 0; cc < 16; cc++) {
            int c = (tid >> 5) + cc * 16;
#pragma unroll
            for (int rr = 0; rr < 4; rr++) {
                int r = (tid & 31) + rr * 32;
                uint32_t w = stage[r * EP_LD + c];
                long long o = ob + (long long)(bn + c) * SEQ + sbase + r;
                Ch[o] = __ushort_as_half((unsigned short)(w & 0xFFFF));
                Cl[o] = __ushort_as_half((unsigned short)(w >> 16));
            }
        }
    }
}

// ------------- fp32 -> fp16 hi/lo split (single fused launch) --------------
__global__ __launch_bounds__(256)
void split_all_kernel(const float* __restrict__ q, const float* __restrict__ k,
                      const float* __restrict__ v, const float* __restrict__ wq,
                      const float* __restrict__ wk, const float* __restrict__ wv,
                      __half* __restrict__ qh, __half* __restrict__ kh,
                      __half* __restrict__ vh, __half* __restrict__ wqh,
                      __half* __restrict__ wkh, __half* __restrict__ wvh)
{
    int b = blockIdx.x;
    const float* x;
    __half* h;
    long long loff;
    int off;
    if      (b < 8192)  { x = q;  h = qh;  loff = N_IN; off = b; }
    else if (b < 16384) { x = k;  h = kh;  loff = N_IN; off = b - 8192; }
    else if (b < 24576) { x = v;  h = vh;  loff = N_IN; off = b - 16384; }
    else if (b < 25600) { x = wq; h = wqh; loff = N_W;  off = b - 24576; }
    else if (b < 26624) { x = wk; h = wkh; loff = N_W;  off = b - 25600; }
    else                { x = wv; h = wvh; loff = N_W;  off = b - 26624; }

    int i = off * 1024 + threadIdx.x * 4;
    float4 val = *(const float4*)(x + i);
    float vv[4] = {val.x, val.y, val.z, val.w};
    unsigned short hs[4], ls[4];
#pragma unroll
    for (int j = 0; j < 4; j++) {
        __half hb = __float2half_rn(vv[j]);
        float hf = __half2float(hb);
        __half lb = __float2half_rn(vv[j] - hf);
        hs[j] = __half_as_ushort(hb);
        ls[j] = __half_as_ushort(lb);
    }
    uint2 hw = make_uint2((uint32_t)hs[0] | ((uint32_t)hs[1] << 16),
                          (uint32_t)hs[2] | ((uint32_t)hs[3] << 16));
    uint2 lw = make_uint2((uint32_t)ls[0] | ((uint32_t)ls[1] << 16),
                          (uint32_t)ls[2] | ((uint32_t)ls[3] << 16));
    *(uint2*)(h + i) = hw;
    *(uint2*)(h + loff + i) = lw;
}

// ---------------------------------------------------------------------------
extern "C" void kernel_launch(void* const* d_in, const int* in_sizes, int n_in,
                              void* d_out, int out_size)
{
    const float* queries = (const float*)d_in[0];
    const float* keys    = (const float*)d_in[1];
    const float* values  = (const float*)d_in[2];
    const float* Wq      = (const float*)d_in[3];
    const float* bq      = (const float*)d_in[4];
    const float* Wk      = (const float*)d_in[5];
    const float* bk      = (const float*)d_in[6];
    const float* Wv      = (const float*)d_in[7];
    const float* bv      = (const float*)d_in[8];
    float* out = (float*)d_out;

    __half *qi, *ki, *vi, *wq, *wk, *wv, *Q, *Kp, *Vt, *S;
    cudaGetSymbolAddress((void**)&qi, g_qi);
    cudaGetSymbolAddress((void**)&ki, g_ki);
    cudaGetSymbolAddress((void**)&vi, g_vi);
    cudaGetSymbolAddress((void**)&wq, g_wq);
    cudaGetSymbolAddress((void**)&wk, g_wk);
    cudaGetSymbolAddress((void**)&wv, g_wv);
    cudaGetSymbolAddress((void**)&Q,  g_Q);
    cudaGetSymbolAddress((void**)&Kp, g_K);
    cudaGetSymbolAddress((void**)&Vt, g_Vt);
    cudaGetSymbolAddress((void**)&S,  g_S);

    cudaFuncSetAttribute(tc_gemm<1, false, true>,
                         cudaFuncAttributeMaxDynamicSharedMemorySize, SMEM_TOTAL);
    cudaFuncSetAttribute(tc_gemm<2, false, true>,
                         cudaFuncAttributeMaxDynamicSharedMemorySize, SMEM_TOTAL);
    cudaFuncSetAttribute(tc_gemm<1, true, false>,
                         cudaFuncAttributeMaxDynamicSharedMemorySize, SMEM_TOTAL);
    cudaFuncSetAttribute(tc_gemm<0, false, false>,
                         cudaFuncAttributeMaxDynamicSharedMemorySize, SMEM_TOTAL);

    // 0) split inputs + weights into fp16 hi/lo
    split_all_kernel<<<27648, 256>>>(queries, keys, values, Wq, Wk, Wv,
                                     qi, ki, vi, wq, wk, wv);

    const int Mproj = BATCH * SEQ;       // 8192
    dim3 blk(THREADS);

    // 1) projections (M=8192, N=1024, K=1024): A = input (split), B = W (hi only)
    dim3 gp(DIM / BN, Mproj / BM, 1);
    tc_gemm<1, false, true><<<gp, blk, SMEM_TOTAL>>>(
        qi, (long long)N_IN, wq, bq, nullptr, Q, Q + N_IN, DIM, DIM, 0, 0, 0);
    tc_gemm<1, false, true><<<gp, blk, SMEM_TOTAL>>>(
        ki, (long long)N_IN, wk, bk, nullptr, Kp, Kp + N_IN, DIM, DIM, 0, 0, 0);
    tc_gemm<2, false, true><<<gp, blk, SMEM_TOTAL>>>(
        vi, (long long)N_IN, wv, bv, nullptr, Vt, Vt + N_IN, DIM, 0, 0, 0, 0);

    // 2) scores: relu(Q @ K^T) per batch (M=2048, N=2048, K=1024)
    dim3 gs(SEQ / BN, SEQ / BM, BATCH);
    tc_gemm<1, true, false><<<gs, blk, SMEM_TOTAL>>>(
        Q, (long long)N_IN, Kp, nullptr,
        nullptr, S, S + N_S, DIM, SEQ,
        (long long)SEQ * DIM, (long long)SEQ * DIM, (long long)SEQ * SEQ);

    // 3) output: S @ Vt^T per batch (M=2048, N=1024, K=2048)
    dim3 go(DIM / BN, SEQ / BM, BATCH);
    tc_gemm<0, false, false><<<go, blk, SMEM_TOTAL>>>(
        S, (long long)N_S, Vt, nullptr,
        out, nullptr, nullptr, SEQ, DIM,
        (long long)SEQ * SEQ, (long long)DIM * SEQ, (long long)SEQ * DIM);

    (void)in_sizes; (void)n_in; (void)out_size;
}

// round 15
// speedup vs baseline: 2.0073x; 1.3352x over previous
#include <cuda_runtime.h>
#include <cuda_fp16.h>
#include <cstdint>

// ---------------------------------------------------------------------------
// B=4, S=2048, D=1024. All GEMMs on mma.sync.m16n8k16 fp16 tensor cores.
// Precision (R15):
//   Projections: A = input split fp16 hi+lo (2 MMA passes), B = fp16(W), out fp16.
//   Scores:      relu(fp16(Q) @ fp16(K)^T), 1 pass, out fp16.
//   Output:      fp16(S) @ fp16(V)^T, 1 pass, out fp32.
// Runtime is HMMA-issue-bound (tensor pinned ~51% across all schedules), so
// MMA instruction count is the control variable: 86 GMAC vs 120 in R14.
// ---------------------------------------------------------------------------

#define BATCH 4
#define SEQ   2048
#define DIM   1024

#define BM 128
#define BN 256
#define KC 64                       // fp16 per K chunk = 128 bytes/row
#define THREADS 512

#define EP_LD 260                   // epilogue smem row stride (u32)

#define N_IN  ((size_t)BATCH * SEQ * DIM)   // 8388608
#define N_W   ((size_t)DIM * DIM)           // 1048576
#define N_S   ((size_t)BATCH * SEQ * SEQ)   // 16777216

// ---------------- device-global scratch (no allocations allowed) -----------
__device__ __half g_qi[2 * N_IN];   // hi at [0,N), lo at [N,2N)
__device__ __half g_ki[2 * N_IN];
__device__ __half g_vi[2 * N_IN];
__device__ __half g_wq[N_W];
__device__ __half g_wk[N_W];
__device__ __half g_wv[N_W];
__device__ __half g_Q [N_IN];
__device__ __half g_K [N_IN];
__device__ __half g_Vt[N_IN];       // [b][d][s]
__device__ __half g_S [N_S];

// ----------------------------- asm helpers --------------------------------
__device__ __forceinline__ uint32_t smem_u32(const void* p) {
    uint32_t a;
    asm("{ .reg .u64 t; cvta.to.shared.u64 t, %1; cvt.u32.u64 %0, t; }"
        : "=r"(a) : "l"(p));
    return a;
}

__device__ __forceinline__ void cp16(uint32_t dst, const void* src) {
    asm volatile("cp.async.cg.shared.global [%0], [%1], 16;" :: "r"(dst), "l"(src));
}

#define CP_COMMIT() asm volatile("cp.async.commit_group;" ::: "memory")

#define LDSM4(r, addr) \
    asm volatile("ldmatrix.sync.aligned.m8n8.x4.shared.b16 {%0,%1,%2,%3}, [%4];" \
        : "=r"((r)[0]), "=r"((r)[1]), "=r"((r)[2]), "=r"((r)[3]) : "r"(addr))

#define MMA(c, a, b0, b1) \
    asm volatile("mma.sync.aligned.m16n8k16.row.col.f32.f16.f16.f32 " \
        "{%0,%1,%2,%3}, {%4,%5,%6,%7}, {%8,%9}, {%0,%1,%2,%3};" \
        : "+f"((c)[0]), "+f"((c)[1]), "+f"((c)[2]), "+f"((c)[3]) \
        : "r"((a)[0]), "r"((a)[1]), "r"((a)[2]), "r"((a)[3]), "r"(b0), "r"(b1))

// ---------------------------------------------------------------------------
// Tensor-core GEMM: C[M,N] = A[M,K] @ B[N,K]^T.
// SPLITA: A has lo plane at A+dA, 2 MMA passes; else 1 pass.
// MODE 0: fp32 out ; MODE 1: fp16 out row-major ;
// MODE 2: fp16 out transposed per-batch into [b][n][m%SEQ] (Vt).
// 16 warps: warp grid 2(M) x 8(N), warp tile 64x32. 3-stage cp.async.
// ---------------------------------------------------------------------------
template <int MODE, bool SPLITA, bool RELU, bool BIAS>
__global__ __launch_bounds__(THREADS, 1)
void tc_gemm(const __half* __restrict__ A, long long dA,
             const __half* __restrict__ B,
             const float* __restrict__ bias,
             float* __restrict__ Cf, __half* __restrict__ Ch,
             int K, int ldc, long long sA, long long sB, long long sC)
{
    constexpr uint32_t OFF_AL = 16384u;                       // split only
    constexpr uint32_t OFF_B  = SPLITA ? 32768u : 16384u;
    constexpr uint32_t STB    = SPLITA ? 65536u : 49152u;     // stage bytes

    extern __shared__ char smem[];
    const uint32_t su = smem_u32(smem);
    const int tid  = threadIdx.x;
    const int lane = tid & 31;
    const int wid  = tid >> 5;
    const int warp_m = (wid & 1) * 64;
    const int warp_n = (wid >> 1) * 32;
    const int bm = blockIdx.y * BM;
    const int bn = blockIdx.x * BN;
    const int z  = blockIdx.z;
    A += (long long)z * sA;
    B += (long long)z * sB;

    float acc[4][4][4];
#pragma unroll
    for (int i = 0; i < 4; i++)
#pragma unroll
        for (int j = 0; j < 4; j++)
#pragma unroll
            for (int k = 0; k < 4; k++) acc[i][j][k] = 0.0f;

    const int nc = K / KC;

    auto LOAD = [&](int chunk) {
        uint32_t sb = su + (uint32_t)(chunk % 3) * STB;
        int kt = chunk * KC;
#pragma unroll
        for (int it = 0; it < (SPLITA ? 8 : 6); it++) {
            int lin = it * THREADS + tid;
            const __half* gp;
            uint32_t toff;
            int c;
            if (SPLITA) {
                if (it < 2)      { c = lin;        gp = A +      (long long)(bm + (c >> 3)) * K; toff = 0; }
                else if (it < 4) { c = lin - 1024; gp = A + dA + (long long)(bm + (c >> 3)) * K; toff = OFF_AL; }
                else             { c = lin - 2048; gp = B +      (long long)(bn + (c >> 3)) * K; toff = OFF_B; }
            } else {
                if (it < 2)      { c = lin;        gp = A +      (long long)(bm + (c >> 3)) * K; toff = 0; }
                else             { c = lin - 1024; gp = B +      (long long)(bn + (c >> 3)) * K; toff = OFF_B; }
            }
            int row = c >> 3;
            int c16 = c & 7;
            uint32_t dst = sb + toff + (uint32_t)row * 128u +
                           (uint32_t)((c16 ^ (row & 7)) << 4);
            cp16(dst, gp + kt + c16 * 8);
        }
        CP_COMMIT();
    };

    LOAD(0); LOAD(1);

    // per-lane ldmatrix addressing
    const int arow  = ((lane >> 3) & 1) * 8 + (lane & 7);
    const int chalf = lane >> 4;
    const int swz   = lane & 7;

    for (int i = 0; i < nc; i++) {
        if (i + 1 < nc) asm volatile("cp.async.wait_group 1;" ::: "memory");
        else            asm volatile("cp.async.wait_group 0;" ::: "memory");
        __syncthreads();

        if (i + 2 < nc) LOAD(i + 2);

        const uint32_t sb = su + (uint32_t)(i % 3) * STB;
        const uint32_t aRow = sb +         (uint32_t)(warp_m + arow) * 128u;
        const uint32_t bRow = sb + OFF_B + (uint32_t)(warp_n + arow) * 128u;

#pragma unroll
        for (int ks = 0; ks < 4; ks++) {
            const uint32_t cb = (uint32_t)(((ks * 2 + chalf) ^ swz) << 4);
            uint32_t fb[2][4];
#pragma unroll
            for (int jn = 0; jn < 2; jn++)
                LDSM4(fb[jn], bRow + jn * 2048u + cb);
#pragma unroll
            for (int im = 0; im < 4; im++) {
                uint32_t fah[4];
                LDSM4(fah, aRow + im * 2048u + cb);
#pragma unroll
                for (int jn = 0; jn < 2; jn++) {
                    MMA(acc[im][2 * jn],     fah, fb[jn][0], fb[jn][2]);
                    MMA(acc[im][2 * jn + 1], fah, fb[jn][1], fb[jn][3]);
                }
                if (SPLITA) {
                    uint32_t fal[4];
                    LDSM4(fal, aRow + OFF_AL + im * 2048u + cb);
#pragma unroll
                    for (int jn = 0; jn < 2; jn++) {
                        MMA(acc[im][2 * jn],     fal, fb[jn][0], fb[jn][2]);
                        MMA(acc[im][2 * jn + 1], fal, fb[jn][1], fb[jn][3]);
                    }
                }
            }
        }
    }
    __syncthreads();   // protect smem reuse by epilogue

    // ---- epilogue: regs -> smem stage (bias/relu/convert) -> coalesced gmem ----
    uint32_t* stage = (uint32_t*)smem;
#pragma unroll
    for (int im = 0; im < 4; im++) {
#pragma unroll
        for (int j8 = 0; j8 < 4; j8++) {
            int r0 = warp_m + im * 16 + (lane >> 2);
            int c0 = warp_n + j8 * 8 + (lane & 3) * 2;
#pragma unroll
            for (int half = 0; half < 2; half++) {
                int r = r0 + half * 8;
#pragma unroll
                for (int cc = 0; cc < 2; cc++) {
                    float v = acc[im][j8][half * 2 + cc];
                    int c = c0 + cc;
                    if (BIAS) v += bias[bn + c];
                    if (RELU) v = fmaxf(v, 0.0f);
                    uint32_t w;
                    if (MODE == 0) w = __float_as_uint(v);
                    else           w = (uint32_t)__half_as_ushort(__float2half_rn(v));
                    stage[r * EP_LD + c] = w;
                }
            }
        }
    }
    __syncthreads();

    if (MODE == 0) {
        float* Cp = Cf + (long long)z * sC;
#pragma unroll 4
        for (int k2 = 0; k2 < 64; k2++) {
            int idx = tid + k2 * THREADS;
            int r = idx >> 8, c = idx & 255;
            Cp[(long long)(bm + r) * ldc + bn + c] =
                __uint_as_float(stage[r * EP_LD + c]);
        }
    } else if (MODE == 1) {
        __half* ChP = Ch + (long long)z * sC;
#pragma unroll 4
        for (int k2 = 0; k2 < 32; k2++) {
            int p = tid + k2 * THREADS;
            int r = p >> 7, cp2 = (p & 127) * 2;
            uint32_t w = (stage[r * EP_LD + cp2] & 0xFFFFu) |
                         (stage[r * EP_LD + cp2 + 1] << 16);
            *(uint32_t*)(ChP + (long long)(bm + r) * ldc + bn + cp2) = w;
        }
    } else {
        // Vt[b][d][s]: b = bm/SEQ, d = bn+c, s = bm%SEQ + r
        long long ob = (long long)(bm >> 11) * ((long long)DIM * SEQ);
        int sbase = bm & (SEQ - 1);
#pragma unroll 1
        for (int cc = 0; cc < 16; cc++) {
            int c = (tid >> 5) + cc * 16;
#pragma unroll
            for (int rr = 0; rr < 4; rr++) {
                int r = (tid & 31) + rr * 32;
                Ch[ob + (long long)(bn + c) * SEQ + sbase + r] =
                    __ushort_as_half((unsigned short)(stage[r * EP_LD + c] & 0xFFFFu));
            }
        }
    }
}

// ----- fp32 -> fp16 split (inputs: hi+lo; weights: hi only), one launch ----
__global__ __launch_bounds__(256)
void split_all_kernel(const float* __restrict__ q, const float* __restrict__ k,
                      const float* __restrict__ v, const float* __restrict__ wq,
                      const float* __restrict__ wk, const float* __restrict__ wv,
                      __half* __restrict__ qh, __half* __restrict__ kh,
                      __half* __restrict__ vh, __half* __restrict__ wqh,
                      __half* __restrict__ wkh, __half* __restrict__ wvh)
{
    int b = blockIdx.x;
    const float* x;
    __half* h;
    bool wlo;
    int off;
    if      (b < 8192)  { x = q;  h = qh;  wlo = true;  off = b; }
    else if (b < 16384) { x = k;  h = kh;  wlo = true;  off = b - 8192; }
    else if (b < 24576) { x = v;  h = vh;  wlo = true;  off = b - 16384; }
    else if (b < 25600) { x = wq; h = wqh; wlo = false; off = b - 24576; }
    else if (b < 26624) { x = wk; h = wkh; wlo = false; off = b - 25600; }
    else                { x = wv; h = wvh; wlo = false; off = b - 26624; }

    int i = off * 1024 + threadIdx.x * 4;
    float4 val = *(const float4*)(x + i);
    float vv[4] = {val.x, val.y, val.z, val.w};
    unsigned short hs[4], ls[4];
#pragma unroll
    for (int j = 0; j < 4; j++) {
        __half hb = __float2half_rn(vv[j]);
        float hf = __half2float(hb);
        __half lb = __float2half_rn(vv[j] - hf);
        hs[j] = __half_as_ushort(hb);
        ls[j] = __half_as_ushort(lb);
    }
    uint2 hw = make_uint2((uint32_t)hs[0] | ((uint32_t)hs[1] << 16),
                          (uint32_t)hs[2] | ((uint32_t)hs[3] << 16));
    *(uint2*)(h + i) = hw;
    if (wlo) {
        uint2 lw = make_uint2((uint32_t)ls[0] | ((uint32_t)ls[1] << 16),
                              (uint32_t)ls[2] | ((uint32_t)ls[3] << 16));
        *(uint2*)(h + N_IN + i) = lw;
    }
}

// ---------------------------------------------------------------------------
extern "C" void kernel_launch(void* const* d_in, const int* in_sizes, int n_in,
                              void* d_out, int out_size)
{
    const float* queries = (const float*)d_in[0];
    const float* keys    = (const float*)d_in[1];
    const float* values  = (const float*)d_in[2];
    const float* Wq      = (const float*)d_in[3];
    const float* bq      = (const float*)d_in[4];
    const float* Wk      = (const float*)d_in[5];
    const float* bk      = (const float*)d_in[6];
    const float* Wv      = (const float*)d_in[7];
    const float* bv      = (const float*)d_in[8];
    float* out = (float*)d_out;

    __half *qi, *ki, *vi, *wq, *wk, *wv, *Q, *Kp, *Vt, *S;
    cudaGetSymbolAddress((void**)&qi, g_qi);
    cudaGetSymbolAddress((void**)&ki, g_ki);
    cudaGetSymbolAddress((void**)&vi, g_vi);
    cudaGetSymbolAddress((void**)&wq, g_wq);
    cudaGetSymbolAddress((void**)&wk, g_wk);
    cudaGetSymbolAddress((void**)&wv, g_wv);
    cudaGetSymbolAddress((void**)&Q,  g_Q);
    cudaGetSymbolAddress((void**)&Kp, g_K);
    cudaGetSymbolAddress((void**)&Vt, g_Vt);
    cudaGetSymbolAddress((void**)&S,  g_S);

    const int SM_SPLIT = 3 * 65536;   // 192 KB
    const int SM_SINGLE = 3 * 49152;  // 144 KB
    cudaFuncSetAttribute(tc_gemm<1, true, false, true>,
                         cudaFuncAttributeMaxDynamicSharedMemorySize, SM_SPLIT);
    cudaFuncSetAttribute(tc_gemm<2, true, false, true>,
                         cudaFuncAttributeMaxDynamicSharedMemorySize, SM_SPLIT);
    cudaFuncSetAttribute(tc_gemm<1, false, true, false>,
                         cudaFuncAttributeMaxDynamicSharedMemorySize, SM_SINGLE);
    cudaFuncSetAttribute(tc_gemm<0, false, false, false>,
                         cudaFuncAttributeMaxDynamicSharedMemorySize, SM_SINGLE);

    // 0) split inputs (hi+lo) + weights (hi) to fp16
    split_all_kernel<<<27648, 256>>>(queries, keys, values, Wq, Wk, Wv,
                                     qi, ki, vi, wq, wk, wv);

    const int Mproj = BATCH * SEQ;       // 8192
    dim3 blk(THREADS);

    // 1) projections (M=8192, N=1024, K=1024), 2-pass A, fp16 out
    dim3 gp(DIM / BN, Mproj / BM, 1);
    tc_gemm<1, true, false, true><<<gp, blk, SM_SPLIT>>>(
        qi, (long long)N_IN, wq, bq, nullptr, Q, DIM, DIM, 0, 0, 0);
    tc_gemm<1, true, false, true><<<gp, blk, SM_SPLIT>>>(
        ki, (long long)N_IN, wk, bk, nullptr, Kp, DIM, DIM, 0, 0, 0);
    tc_gemm<2, true, false, true><<<gp, blk, SM_SPLIT>>>(
        vi, (long long)N_IN, wv, bv, nullptr, Vt, DIM, 0, 0, 0, 0);

    // 2) scores: relu(Q @ K^T) per batch, 1-pass, fp16 out
    dim3 gs(SEQ / BN, SEQ / BM, BATCH);
    tc_gemm<1, false, true, false><<<gs, blk, SM_SINGLE>>>(
        Q, 0, Kp, nullptr, nullptr, S, DIM, SEQ,
        (long long)SEQ * DIM, (long long)SEQ * DIM, (long long)SEQ * SEQ);

    // 3) output: S @ Vt^T per batch, 1-pass, fp32 out
    dim3 go(DIM / BN, SEQ / BM, BATCH);
    tc_gemm<0, false, false, false><<<go, blk, SM_SINGLE>>>(
        S, 0, Vt, nullptr, out, nullptr, SEQ, DIM,
        (long long)SEQ * SEQ, (long long)DIM * SEQ, (long long)SEQ * DIM);

    (void)in_sizes; (void)n_in; (void)out_size;
}

// round 16
// speedup vs baseline: 2.6273x; 1.3089x over previous
#include <cuda_runtime.h>
#include <cuda_fp16.h>
#include <cstdint>

// ---------------------------------------------------------------------------
// B=4, S=2048, D=1024. All GEMMs on mma.sync.m16n8k16 fp16 tensor cores,
// single pass everywhere (60.3 GMAC = minimum). Evidence across R6..R15:
// legacy mma.sync on sm_103a is issue-capped (~51% tensor regardless of
// schedule/occupancy), so runtime tracks MMA instruction count; measured
// per-operand fp16 rounding contributes ~2e-4 in quadrature -> est 6e-4.
// 512 threads / 16 warps, CTA 128x256, warp 64x32, KC=64, 3-stage cp.async.
// ---------------------------------------------------------------------------

#define BATCH 4
#define SEQ   2048
#define DIM   1024

#define BM 128
#define BN 256
#define KC 64                       // fp16 per K chunk = 128 bytes/row
#define THREADS 512

#define OFF_B  16384u               // A: 16 KB, B: 32 KB
#define STB    49152u               // 48 KB/stage
#define SMEM_TOTAL (3 * 49152)      // 144 KB

#define EP_LD 260                   // epilogue smem row stride (u32)

#define N_IN  ((size_t)BATCH * SEQ * DIM)   // 8388608
#define N_W   ((size_t)DIM * DIM)           // 1048576
#define N_S   ((size_t)BATCH * SEQ * SEQ)   // 16777216

// ---------------- device-global scratch (no allocations allowed) -----------
__device__ __half g_qi[N_IN];
__device__ __half g_ki[N_IN];
__device__ __half g_vi[N_IN];
__device__ __half g_wq[N_W];
__device__ __half g_wk[N_W];
__device__ __half g_wv[N_W];
__device__ __half g_Q [N_IN];
__device__ __half g_K [N_IN];
__device__ __half g_Vt[N_IN];       // [b][d][s]
__device__ __half g_S [N_S];

// ----------------------------- asm helpers --------------------------------
__device__ __forceinline__ uint32_t smem_u32(const void* p) {
    uint32_t a;
    asm("{ .reg .u64 t; cvta.to.shared.u64 t, %1; cvt.u32.u64 %0, t; }"
        : "=r"(a) : "l"(p));
    return a;
}

__device__ __forceinline__ void cp16(uint32_t dst, const void* src) {
    asm volatile("cp.async.cg.shared.global [%0], [%1], 16;" :: "r"(dst), "l"(src));
}

#define CP_COMMIT() asm volatile("cp.async.commit_group;" ::: "memory")

#define LDSM4(r, addr) \
    asm volatile("ldmatrix.sync.aligned.m8n8.x4.shared.b16 {%0,%1,%2,%3}, [%4];" \
        : "=r"((r)[0]), "=r"((r)[1]), "=r"((r)[2]), "=r"((r)[3]) : "r"(addr))

#define MMA(c, a, b0, b1) \
    asm volatile("mma.sync.aligned.m16n8k16.row.col.f32.f16.f16.f32 " \
        "{%0,%1,%2,%3}, {%4,%5,%6,%7}, {%8,%9}, {%0,%1,%2,%3};" \
        : "+f"((c)[0]), "+f"((c)[1]), "+f"((c)[2]), "+f"((c)[3]) \
        : "r"((a)[0]), "r"((a)[1]), "r"((a)[2]), "r"((a)[3]), "r"(b0), "r"(b1))

// ---------------------------------------------------------------------------
// Tensor-core GEMM: C[M,N] = A[M,K] @ B[N,K]^T, single fp16 pass.
// MODE 0: fp32 out ; MODE 1: fp16 out row-major ;
// MODE 2: fp16 out transposed per-batch into [b][n][m%SEQ] (Vt).
// 16 warps: warp grid 2(M) x 8(N), warp tile 64x32. 3-stage cp.async.
// ---------------------------------------------------------------------------
template <int MODE, bool RELU, bool BIAS>
__global__ __launch_bounds__(THREADS, 1)
void tc_gemm(const __half* __restrict__ A,
             const __half* __restrict__ B,
             const float* __restrict__ bias,
             float* __restrict__ Cf, __half* __restrict__ Ch,
             int K, int ldc, long long sA, long long sB, long long sC)
{
    extern __shared__ char smem[];
    const uint32_t su = smem_u32(smem);
    const int tid  = threadIdx.x;
    const int lane = tid & 31;
    const int wid  = tid >> 5;
    const int warp_m = (wid & 1) * 64;
    const int warp_n = (wid >> 1) * 32;
    const int bm = blockIdx.y * BM;
    const int bn = blockIdx.x * BN;
    const int z  = blockIdx.z;
    A += (long long)z * sA;
    B += (long long)z * sB;

    float acc[4][4][4];
#pragma unroll
    for (int i = 0; i < 4; i++)
#pragma unroll
        for (int j = 0; j < 4; j++)
#pragma unroll
            for (int k = 0; k < 4; k++) acc[i][j][k] = 0.0f;

    const int nc = K / KC;

    auto LOAD = [&](int chunk) {
        uint32_t sb = su + (uint32_t)(chunk % 3) * STB;
        int kt = chunk * KC;
#pragma unroll
        for (int it = 0; it < 6; it++) {
            int lin = it * THREADS + tid;
            const __half* gp;
            uint32_t toff;
            int c;
            if (it < 2) { c = lin;        gp = A + (long long)(bm + (c >> 3)) * K; toff = 0; }
            else        { c = lin - 1024; gp = B + (long long)(bn + (c >> 3)) * K; toff = OFF_B; }
            int row = c >> 3;
            int c16 = c & 7;
            uint32_t dst = sb + toff + (uint32_t)row * 128u +
                           (uint32_t)((c16 ^ (row & 7)) << 4);
            cp16(dst, gp + kt + c16 * 8);
        }
        CP_COMMIT();
    };

    LOAD(0); LOAD(1);

    // per-lane ldmatrix addressing
    const int arow  = ((lane >> 3) & 1) * 8 + (lane & 7);
    const int chalf = lane >> 4;
    const int swz   = lane & 7;

    for (int i = 0; i < nc; i++) {
        if (i + 1 < nc) asm volatile("cp.async.wait_group 1;" ::: "memory");
        else            asm volatile("cp.async.wait_group 0;" ::: "memory");
        __syncthreads();

        if (i + 2 < nc) LOAD(i + 2);

        const uint32_t sb = su + (uint32_t)(i % 3) * STB;
        const uint32_t aRow = sb +         (uint32_t)(warp_m + arow) * 128u;
        const uint32_t bRow = sb + OFF_B + (uint32_t)(warp_n + arow) * 128u;

#pragma unroll
        for (int ks = 0; ks < 4; ks++) {
            const uint32_t cb = (uint32_t)(((ks * 2 + chalf) ^ swz) << 4);
            uint32_t fb[2][4];
#pragma unroll
            for (int jn = 0; jn < 2; jn++)
                LDSM4(fb[jn], bRow + jn * 2048u + cb);
#pragma unroll
            for (int im = 0; im < 4; im++) {
                uint32_t fa[4];
                LDSM4(fa, aRow + im * 2048u + cb);
#pragma unroll
                for (int jn = 0; jn < 2; jn++) {
                    MMA(acc[im][2 * jn],     fa, fb[jn][0], fb[jn][2]);
                    MMA(acc[im][2 * jn + 1], fa, fb[jn][1], fb[jn][3]);
                }
            }
        }
    }
    __syncthreads();   // protect smem reuse by epilogue

    // ---- epilogue: regs -> smem stage (bias/relu/convert) -> coalesced gmem ----
    uint32_t* stage = (uint32_t*)smem;
#pragma unroll
    for (int im = 0; im < 4; im++) {
#pragma unroll
        for (int j8 = 0; j8 < 4; j8++) {
            int r0 = warp_m + im * 16 + (lane >> 2);
            int c0 = warp_n + j8 * 8 + (lane & 3) * 2;
#pragma unroll
            for (int half = 0; half < 2; half++) {
                int r = r0 + half * 8;
#pragma unroll
                for (int cc = 0; cc < 2; cc++) {
                    float v = acc[im][j8][half * 2 + cc];
                    int c = c0 + cc;
                    if (BIAS) v += bias[bn + c];
                    if (RELU) v = fmaxf(v, 0.0f);
                    uint32_t w;
                    if (MODE == 0) w = __float_as_uint(v);
                    else           w = (uint32_t)__half_as_ushort(__float2half_rn(v));
                    stage[r * EP_LD + c] = w;
                }
            }
        }
    }
    __syncthreads();

    if (MODE == 0) {
        float* Cp = Cf + (long long)z * sC;
#pragma unroll 4
        for (int k2 = 0; k2 < 64; k2++) {
            int idx = tid + k2 * THREADS;
            int r = idx >> 8, c = idx & 255;
            Cp[(long long)(bm + r) * ldc + bn + c] =
                __uint_as_float(stage[r * EP_LD + c]);
        }
    } else if (MODE == 1) {
        __half* ChP = Ch + (long long)z * sC;
#pragma unroll 4
        for (int k2 = 0; k2 < 32; k2++) {
            int p = tid + k2 * THREADS;
            int r = p >> 7, cp2 = (p & 127) * 2;
            uint32_t w = (stage[r * EP_LD + cp2] & 0xFFFFu) |
                         (stage[r * EP_LD + cp2 + 1] << 16);
            *(uint32_t*)(ChP + (long long)(bm + r) * ldc + bn + cp2) = w;
        }
    } else {
        // Vt[b][d][s]: b = bm/SEQ, d = bn+c, s = bm%SEQ + r
        long long ob = (long long)(bm >> 11) * ((long long)DIM * SEQ);
        int sbase = bm & (SEQ - 1);
#pragma unroll 1
        for (int cc = 0; cc < 16; cc++) {
            int c = (tid >> 5) + cc * 16;
#pragma unroll
            for (int rr = 0; rr < 4; rr++) {
                int r = (tid & 31) + rr * 32;
                Ch[ob + (long long)(bn + c) * SEQ + sbase + r] =
                    __ushort_as_half((unsigned short)(stage[r * EP_LD + c] & 0xFFFFu));
            }
        }
    }
}

// ----------- fp32 -> fp16 convert (all six tensors, one launch) ------------
__global__ __launch_bounds__(256)
void conv_all_kernel(const float* __restrict__ q, const float* __restrict__ k,
                     const float* __restrict__ v, const float* __restrict__ wq,
                     const float* __restrict__ wk, const float* __restrict__ wv,
                     __half* __restrict__ qh, __half* __restrict__ kh,
                     __half* __restrict__ vh, __half* __restrict__ wqh,
                     __half* __restrict__ wkh, __half* __restrict__ wvh)
{
    int b = blockIdx.x;
    const float* x;
    __half* h;
    int off;
    if      (b < 8192)  { x = q;  h = qh;  off = b; }
    else if (b < 16384) { x = k;  h = kh;  off = b - 8192; }
    else if (b < 24576) { x = v;  h = vh;  off = b - 16384; }
    else if (b < 25600) { x = wq; h = wqh; off = b - 24576; }
    else if (b < 26624) { x = wk; h = wkh; off = b - 25600; }
    else                { x = wv; h = wvh; off = b - 26624; }

    int i = off * 1024 + threadIdx.x * 4;
    float4 val = *(const float4*)(x + i);
    unsigned short hs[4];
    hs[0] = __half_as_ushort(__float2half_rn(val.x));
    hs[1] = __half_as_ushort(__float2half_rn(val.y));
    hs[2] = __half_as_ushort(__float2half_rn(val.z));
    hs[3] = __half_as_ushort(__float2half_rn(val.w));
    uint2 hw = make_uint2((uint32_t)hs[0] | ((uint32_t)hs[1] << 16),
                          (uint32_t)hs[2] | ((uint32_t)hs[3] << 16));
    *(uint2*)(h + i) = hw;
}

// ---------------------------------------------------------------------------
extern "C" void kernel_launch(void* const* d_in, const int* in_sizes, int n_in,
                              void* d_out, int out_size)
{
    const float* queries = (const float*)d_in[0];
    const float* keys    = (const float*)d_in[1];
    const float* values  = (const float*)d_in[2];
    const float* Wq      = (const float*)d_in[3];
    const float* bq      = (const float*)d_in[4];
    const float* Wk      = (const float*)d_in[5];
    const float* bk      = (const float*)d_in[6];
    const float* Wv      = (const float*)d_in[7];
    const float* bv      = (const float*)d_in[8];
    float* out = (float*)d_out;

    __half *qi, *ki, *vi, *wq, *wk, *wv, *Q, *Kp, *Vt, *S;
    cudaGetSymbolAddress((void**)&qi, g_qi);
    cudaGetSymbolAddress((void**)&ki, g_ki);
    cudaGetSymbolAddress((void**)&vi, g_vi);
    cudaGetSymbolAddress((void**)&wq, g_wq);
    cudaGetSymbolAddress((void**)&wk, g_wk);
    cudaGetSymbolAddress((void**)&wv, g_wv);
    cudaGetSymbolAddress((void**)&Q,  g_Q);
    cudaGetSymbolAddress((void**)&Kp, g_K);
    cudaGetSymbolAddress((void**)&Vt, g_Vt);
    cudaGetSymbolAddress((void**)&S,  g_S);

    cudaFuncSetAttribute(tc_gemm<1, false, true>,
                         cudaFuncAttributeMaxDynamicSharedMemorySize, SMEM_TOTAL);
    cudaFuncSetAttribute(tc_gemm<2, false, true>,
                         cudaFuncAttributeMaxDynamicSharedMemorySize, SMEM_TOTAL);
    cudaFuncSetAttribute(tc_gemm<1, true, false>,
                         cudaFuncAttributeMaxDynamicSharedMemorySize, SMEM_TOTAL);
    cudaFuncSetAttribute(tc_gemm<0, false, false>,
                         cudaFuncAttributeMaxDynamicSharedMemorySize, SMEM_TOTAL);

    // 0) convert inputs + weights to fp16
    conv_all_kernel<<<27648, 256>>>(queries, keys, values, Wq, Wk, Wv,
                                    qi, ki, vi, wq, wk, wv);

    const int Mproj = BATCH * SEQ;       // 8192
    dim3 blk(THREADS);

    // 1) projections (M=8192, N=1024, K=1024), 1-pass, fp16 out
    dim3 gp(DIM / BN, Mproj / BM, 1);
    tc_gemm<1, false, true><<<gp, blk, SMEM_TOTAL>>>(
        qi, wq, bq, nullptr, Q, DIM, DIM, 0, 0, 0);
    tc_gemm<1, false, true><<<gp, blk, SMEM_TOTAL>>>(
        ki, wk, bk, nullptr, Kp, DIM, DIM, 0, 0, 0);
    tc_gemm<2, false, true><<<gp, blk, SMEM_TOTAL>>>(
        vi, wv, bv, nullptr, Vt, DIM, 0, 0, 0, 0);

    // 2) scores: relu(Q @ K^T) per batch, 1-pass, fp16 out
    dim3 gs(SEQ / BN, SEQ / BM, BATCH);
    tc_gemm<1, true, false><<<gs, blk, SMEM_TOTAL>>>(
        Q, Kp, nullptr, nullptr, S, DIM, SEQ,
        (long long)SEQ * DIM, (long long)SEQ * DIM, (long long)SEQ * SEQ);

    // 3) output: S @ Vt^T per batch, 1-pass, fp32 out
    dim3 go(DIM / BN, SEQ / BM, BATCH);
    tc_gemm<0, false, false><<<go, blk, SMEM_TOTAL>>>(
        S, Vt, nullptr, out, nullptr, SEQ, DIM,
        (long long)SEQ * SEQ, (long long)DIM * SEQ, (long long)SEQ * DIM);

    (void)in_sizes; (void)n_in; (void)out_size;
}